// round 5
// baseline (speedup 1.0000x reference)
#include <cuda_runtime.h>

// ADDLoss, f32x2 SoA-pair version with load-ahead scheduling (MLP) and
// 4 independent accumulators (ILP). R4 lesson: 40-reg budget serialized the
// 12 LDG.128s per warp-iteration -> stall-bound at issue=58%. Give ptxas a
// 64-reg budget and explicit front-batched loads.

#define BATCH      16384
#define NPTS       500
#define NPAIRS     250
#define NQUADS     125
#define NOBJ       30
#define OBJ_STRIDE 256                  // u64 pairs per object (padded)
#define WARPS_PB   4
#define THREADS_PB (WARPS_PB * 32)      // 128
#define NBLOCKS    (BATCH / WARPS_PB)   // 4096

#define FP_SCALE     68719476736.0      // 2^36
#define INV_FP_SCALE (1.0 / 68719476736.0)

typedef unsigned long long u64;

__device__ u64 g_px[NOBJ * OBJ_STRIDE];
__device__ u64 g_py[NOBJ * OBJ_STRIDE];
__device__ u64 g_pz[NOBJ * OBJ_STRIDE];
__device__ u64 g_sum;
__device__ unsigned int g_count;

__device__ __forceinline__ u64 pack2(float lo, float hi) {
    u64 d; asm("mov.b64 %0, {%1, %2};" : "=l"(d) : "f"(lo), "f"(hi)); return d;
}
__device__ __forceinline__ void unpack2(float& lo, float& hi, u64 v) {
    asm("mov.b64 {%0, %1}, %2;" : "=f"(lo), "=f"(hi) : "l"(v));
}
__device__ __forceinline__ u64 mul2(u64 a, u64 b) {
    u64 d; asm("mul.rn.f32x2 %0, %1, %2;" : "=l"(d) : "l"(a), "l"(b)); return d;
}
__device__ __forceinline__ u64 add2(u64 a, u64 b) {
    u64 d; asm("add.rn.f32x2 %0, %1, %2;" : "=l"(d) : "l"(a), "l"(b)); return d;
}
__device__ __forceinline__ u64 fma2(u64 a, u64 b, u64 c) {
    u64 d; asm("fma.rn.f32x2 %0, %1, %2, %3;" : "=l"(d) : "l"(a), "l"(b), "l"(c)); return d;
}
__device__ __forceinline__ float sqrt_approx(float x) {
    float r; asm("sqrt.approx.f32 %0, %1;" : "=f"(r) : "f"(fmaxf(x, 0.0f))); return r;
}

// ---- prep: AoS points -> SoA u64 pairs -------------------------------------
__global__ void addloss_prep(const float* __restrict__ points)
{
    const int o = blockIdx.x;
    const int j = threadIdx.x;
    if (j >= NPAIRS) return;
    const float* p = points + (size_t)o * (NPTS * 3) + 6 * j;
    g_px[o * OBJ_STRIDE + j] = pack2(p[0], p[3]);
    g_py[o * OBJ_STRIDE + j] = pack2(p[1], p[4]);
    g_pz[o * OBJ_STRIDE + j] = pack2(p[2], p[5]);
}

// ---- main ------------------------------------------------------------------
__global__ __launch_bounds__(THREADS_PB, 4)   // ~64-reg budget
void addloss_fused(const float* __restrict__ pred_r,
                   const float* __restrict__ pred_t,
                   const float* __restrict__ gt_r,
                   const float* __restrict__ gt_t,
                   const int*   __restrict__ obj_ids,
                   float*       __restrict__ out)
{
    const int warp_in_blk = threadIdx.x >> 5;
    const int lane        = threadIdx.x & 31;
    const int b           = blockIdx.x * WARPS_PB + warp_in_blk;

    __shared__ float sh_val[WARPS_PB];

    // ---- per-batch-element setup (redundant across lanes; amortized) ----
    const float4 qp = reinterpret_cast<const float4*>(pred_r)[b];
    const float4 qg = reinterpret_cast<const float4*>(gt_r)[b];

    float pw = qp.x, px_ = qp.y, py_ = qp.z, pz_ = qp.w;
    float p_x2 = px_*px_, p_y2 = py_*py_, p_z2 = pz_*pz_;
    float p_xy = px_*py_, p_xz = px_*pz_, p_yz = py_*pz_;
    float p_wx = pw*px_,  p_wy = pw*py_,  p_wz = pw*pz_;
    float gw = qg.x, gx_ = qg.y, gy_ = qg.z, gz_ = qg.w;
    float g_x2 = gx_*gx_, g_y2 = gy_*gy_, g_z2 = gz_*gz_;
    float g_xy = gx_*gy_, g_xz = gx_*gz_, g_yz = gy_*gz_;
    float g_wx = gw*gx_,  g_wy = gw*gy_,  g_wz = gw*gz_;

    const float m00 = -2.f*(p_y2 + p_z2 - g_y2 - g_z2);
    const float m01 =  2.f*(p_xy - p_wz - g_xy + g_wz);
    const float m02 =  2.f*(p_xz + p_wy - g_xz - g_wy);
    const float m10 =  2.f*(p_xy + p_wz - g_xy - g_wz);
    const float m11 = -2.f*(p_x2 + p_z2 - g_x2 - g_z2);
    const float m12 =  2.f*(p_yz - p_wx - g_yz + g_wx);
    const float m20 =  2.f*(p_xz - p_wy - g_xz + g_wy);
    const float m21 =  2.f*(p_yz + p_wx - g_yz - g_wx);
    const float m22 = -2.f*(p_x2 + p_y2 - g_x2 - g_y2);

    const float tx = pred_t[3*b+0] - gt_t[3*b+0];
    const float ty = pred_t[3*b+1] - gt_t[3*b+1];
    const float tz = pred_t[3*b+2] - gt_t[3*b+2];
    const float t2s = tx*tx + ty*ty + tz*tz;

    const float s00 = m00*m00 + m10*m10 + m20*m20;
    const float s11 = m01*m01 + m11*m11 + m21*m21;
    const float s22 = m02*m02 + m12*m12 + m22*m22;
    const float s01 = 2.f*(m00*m01 + m10*m11 + m20*m21);
    const float s02 = 2.f*(m00*m02 + m10*m12 + m20*m22);
    const float s12 = 2.f*(m01*m02 + m11*m12 + m21*m22);
    const float c0s = 2.f*(m00*tx + m10*ty + m20*tz);
    const float c1s = 2.f*(m01*tx + m11*ty + m21*tz);
    const float c2s = 2.f*(m02*tx + m12*ty + m22*tz);

    const u64 S00 = pack2(s00, s00), S11 = pack2(s11, s11), S22 = pack2(s22, s22);
    const u64 S01 = pack2(s01, s01), S02 = pack2(s02, s02), S12 = pack2(s12, s12);
    const u64 C0  = pack2(c0s, c0s), C1  = pack2(c1s, c1s), C2  = pack2(c2s, c2s);
    const u64 T2  = pack2(t2s, t2s);

    int oid = obj_ids[b];
    oid = min(max(oid, 0), NOBJ - 1);
    const ulonglong2* __restrict__ BX =
        reinterpret_cast<const ulonglong2*>(g_px) + oid * (OBJ_STRIDE / 2);
    const ulonglong2* __restrict__ BY =
        reinterpret_cast<const ulonglong2*>(g_py) + oid * (OBJ_STRIDE / 2);
    const ulonglong2* __restrict__ BZ =
        reinterpret_cast<const ulonglong2*>(g_pz) + oid * (OBJ_STRIDE / 2);

    float acc0 = 0.f, acc1 = 0.f, acc2 = 0.f, acc3 = 0.f;

    #define PAIR_TERM(PX, PY, PZ, ACC) do {                                    \
        u64 U  = fma2(S02, (PZ), fma2(S01, (PY), mul2(S00, (PX))));            \
        u64 V  = fma2(S12, (PZ), mul2(S11, (PY)));                             \
        u64 W  = mul2(S22, (PZ));                                              \
        u64 A2 = fma2((PZ), W, fma2((PY), V, mul2((PX), U)));                  \
        u64 LIN = fma2(C0, (PX), fma2(C1, (PY), fma2(C2, (PZ), T2)));          \
        u64 B2 = add2(A2, LIN);                                                \
        float a2l, a2h, b2l, b2h;                                              \
        unpack2(a2l, a2h, A2);                                                 \
        unpack2(b2l, b2h, B2);                                                 \
        ACC += (sqrt_approx(a2l) + sqrt_approx(b2l))                           \
             + (sqrt_approx(a2h) + sqrt_approx(b2h));                          \
    } while (0)

    // ---- front-batched loads: 3 quads issued before any compute ----
    const ulonglong2 x0 = BX[lane],      y0 = BY[lane],      z0 = BZ[lane];
    const ulonglong2 x1 = BX[lane + 32], y1 = BY[lane + 32], z1 = BZ[lane + 32];
    const ulonglong2 x2 = BX[lane + 64], y2 = BY[lane + 64], z2 = BZ[lane + 64];

    PAIR_TERM(x0.x, y0.x, z0.x, acc0);
    PAIR_TERM(x0.y, y0.y, z0.y, acc1);
    PAIR_TERM(x1.x, y1.x, z1.x, acc2);
    PAIR_TERM(x1.y, y1.y, z1.y, acc3);

    if (lane < NQUADS - 96) {   // lane < 29: 4th quad
        const ulonglong2 x3 = BX[lane + 96], y3 = BY[lane + 96], z3 = BZ[lane + 96];
        PAIR_TERM(x2.x, y2.x, z2.x, acc0);
        PAIR_TERM(x2.y, y2.y, z2.y, acc1);
        PAIR_TERM(x3.x, y3.x, z3.x, acc2);
        PAIR_TERM(x3.y, y3.y, z3.y, acc3);
    } else {
        PAIR_TERM(x2.x, y2.x, z2.x, acc0);
        PAIR_TERM(x2.y, y2.y, z2.y, acc1);
    }
    #undef PAIR_TERM

    float s = (acc0 + acc1) + (acc2 + acc3);

    #pragma unroll
    for (int off = 16; off > 0; off >>= 1)
        s += __shfl_down_sync(0xffffffffu, s, off);

    if (lane == 0)
        sh_val[warp_in_blk] = s * (1.0f / NPTS) + sqrt_approx(t2s);
    __syncthreads();

    if (threadIdx.x == 0) {
        float blk = 0.f;
        #pragma unroll
        for (int w = 0; w < WARPS_PB; w++) blk += sh_val[w];

        const u64 q = (u64)__double2ll_rn((double)blk * FP_SCALE);
        atomicAdd(&g_sum, q);
        __threadfence();
        const unsigned int ticket = atomicAdd(&g_count, 1u);
        if (ticket == NBLOCKS - 1) {
            const u64 total = atomicExch(&g_sum, 0ULL);  // read + reset for replay
            g_count = 0u;
            out[0] = (float)((double)total * INV_FP_SCALE * (1.0 / BATCH));
        }
    }
}

extern "C" void kernel_launch(void* const* d_in, const int* in_sizes, int n_in,
                              void* d_out, int out_size)
{
    const float* pred_r  = (const float*)d_in[0];
    const float* pred_t  = (const float*)d_in[1];
    const float* gt_r    = (const float*)d_in[2];
    const float* gt_t    = (const float*)d_in[3];
    const int*   obj_ids = (const int*)  d_in[4];
    const float* points  = (const float*)d_in[5];
    float* out = (float*)d_out;

    addloss_prep<<<NOBJ, 256>>>(points);
    addloss_fused<<<NBLOCKS, THREADS_PB>>>(pred_r, pred_t, gt_r, gt_t,
                                           obj_ids, out);
}

// round 6
// speedup vs baseline: 1.0152x; 1.0152x over previous
#include <cuda_runtime.h>

// ADDLoss, three-phase:
//   prep+setup kernel: (a) pack points AoS->SoA u64 pairs (30 blocks)
//                      (b) per-batch coeffs S = M^T M, c = 2 M^T t, t2 (64 blocks),
//                          plus trans-norm term reduced straight into g_sum.
//   hot kernel: per warp = 1 batch elem; load 3 float4 coeffs (broadcast),
//               f32x2 quadratic-form loop over 500 points, deterministic
//               fixed-point integer atomic reduce.

#define BATCH      16384
#define NPTS       500
#define NPAIRS     250
#define NQUADS     125
#define NOBJ       30
#define OBJ_STRIDE 256
#define WARPS_PB   8
#define THREADS_PB (WARPS_PB * 32)      // 256
#define NBLOCKS    (BATCH / WARPS_PB)   // 2048
#define SETUP_BLOCKS (BATCH / 256)      // 64

#define FP_SCALE     68719476736.0      // 2^36
#define INV_FP_SCALE (1.0 / 68719476736.0)

typedef unsigned long long u64;

__device__ u64   g_px[NOBJ * OBJ_STRIDE];
__device__ u64   g_py[NOBJ * OBJ_STRIDE];
__device__ u64   g_pz[NOBJ * OBJ_STRIDE];
__device__ float4 g_coef[BATCH * 3];    // {s00,s11,s22,s01} {s02,s12,c0,c1} {c2,t2,-,-}
__device__ u64   g_sum;
__device__ unsigned int g_count;

__device__ __forceinline__ u64 pack2(float lo, float hi) {
    u64 d; asm("mov.b64 %0, {%1, %2};" : "=l"(d) : "f"(lo), "f"(hi)); return d;
}
__device__ __forceinline__ void unpack2(float& lo, float& hi, u64 v) {
    asm("mov.b64 {%0, %1}, %2;" : "=f"(lo), "=f"(hi) : "l"(v));
}
__device__ __forceinline__ u64 mul2(u64 a, u64 b) {
    u64 d; asm("mul.rn.f32x2 %0, %1, %2;" : "=l"(d) : "l"(a), "l"(b)); return d;
}
__device__ __forceinline__ u64 add2(u64 a, u64 b) {
    u64 d; asm("add.rn.f32x2 %0, %1, %2;" : "=l"(d) : "l"(a), "l"(b)); return d;
}
__device__ __forceinline__ u64 fma2(u64 a, u64 b, u64 c) {
    u64 d; asm("fma.rn.f32x2 %0, %1, %2, %3;" : "=l"(d) : "l"(a), "l"(b), "l"(c)); return d;
}
__device__ __forceinline__ float sqrt_abs(float x) {
    // a2/b2 are >=0 up to rounding; |x| guard folds into MUFU input modifier.
    float r; asm("sqrt.approx.f32 %0, %1;" : "=f"(r) : "f"(fabsf(x))); return r;
}

// ---- phase 1: prep (points pack) + setup (coeffs + trans term) -------------
__global__ __launch_bounds__(256)
void addloss_setup(const float* __restrict__ points,
                   const float* __restrict__ pred_r,
                   const float* __restrict__ pred_t,
                   const float* __restrict__ gt_r,
                   const float* __restrict__ gt_t)
{
    if (blockIdx.x >= SETUP_BLOCKS) {
        // ---- points pack: blocks [64, 94) -> objects [0, 30) ----
        const int o = blockIdx.x - SETUP_BLOCKS;
        const int j = threadIdx.x;
        if (j < NPAIRS) {
            const float* p = points + (size_t)o * (NPTS * 3) + 6 * j;
            g_px[o * OBJ_STRIDE + j] = pack2(p[0], p[3]);
            g_py[o * OBJ_STRIDE + j] = pack2(p[1], p[4]);
            g_pz[o * OBJ_STRIDE + j] = pack2(p[2], p[5]);
        }
        return;
    }

    // ---- per-batch coefficients ----
    const int b = blockIdx.x * 256 + threadIdx.x;

    const float4 qp = reinterpret_cast<const float4*>(pred_r)[b];
    const float4 qg = reinterpret_cast<const float4*>(gt_r)[b];

    float pw = qp.x, px_ = qp.y, py_ = qp.z, pz_ = qp.w;
    float gw = qg.x, gx_ = qg.y, gy_ = qg.z, gz_ = qg.w;

    const float m00 = -2.f*(py_*py_ + pz_*pz_ - gy_*gy_ - gz_*gz_);
    const float m01 =  2.f*(px_*py_ - pw*pz_ - gx_*gy_ + gw*gz_);
    const float m02 =  2.f*(px_*pz_ + pw*py_ - gx_*gz_ - gw*gy_);
    const float m10 =  2.f*(px_*py_ + pw*pz_ - gx_*gy_ - gw*gz_);
    const float m11 = -2.f*(px_*px_ + pz_*pz_ - gx_*gx_ - gz_*gz_);
    const float m12 =  2.f*(py_*pz_ - pw*px_ - gy_*gz_ + gw*gx_);
    const float m20 =  2.f*(px_*pz_ - pw*py_ - gx_*gz_ + gw*gy_);
    const float m21 =  2.f*(py_*pz_ + pw*px_ - gy_*gz_ - gw*gx_);
    const float m22 = -2.f*(px_*px_ + py_*py_ - gx_*gx_ - gy_*gy_);

    const float tx = pred_t[3*b+0] - gt_t[3*b+0];
    const float ty = pred_t[3*b+1] - gt_t[3*b+1];
    const float tz = pred_t[3*b+2] - gt_t[3*b+2];
    const float t2 = tx*tx + ty*ty + tz*tz;

    float4 c0, c1, c2;
    c0.x = m00*m00 + m10*m10 + m20*m20;            // s00
    c0.y = m01*m01 + m11*m11 + m21*m21;            // s11
    c0.z = m02*m02 + m12*m12 + m22*m22;            // s22
    c0.w = 2.f*(m00*m01 + m10*m11 + m20*m21);      // s01
    c1.x = 2.f*(m00*m02 + m10*m12 + m20*m22);      // s02
    c1.y = 2.f*(m01*m02 + m11*m12 + m21*m22);      // s12
    c1.z = 2.f*(m00*tx + m10*ty + m20*tz);         // c0
    c1.w = 2.f*(m01*tx + m11*ty + m21*tz);         // c1
    c2.x = 2.f*(m02*tx + m12*ty + m22*tz);         // c2
    c2.y = t2;
    c2.z = 0.f; c2.w = 0.f;
    g_coef[3*b + 0] = c0;
    g_coef[3*b + 1] = c1;
    g_coef[3*b + 2] = c2;

    // trans-norm contribution: block tree-reduce (fixed order) -> int atomic
    __shared__ float sh[256];
    sh[threadIdx.x] = sqrt_abs(t2);
    __syncthreads();
    #pragma unroll
    for (int st = 128; st > 0; st >>= 1) {
        if (threadIdx.x < st) sh[threadIdx.x] += sh[threadIdx.x + st];
        __syncthreads();
    }
    if (threadIdx.x == 0) {
        const u64 q = (u64)__double2ll_rn((double)sh[0] * FP_SCALE);
        atomicAdd(&g_sum, q);
    }
}

// ---- phase 2: hot kernel ----------------------------------------------------
__global__ __launch_bounds__(THREADS_PB)
void addloss_main(const int* __restrict__ obj_ids, float* __restrict__ out)
{
    const int warp_in_blk = threadIdx.x >> 5;
    const int lane        = threadIdx.x & 31;
    const int b           = blockIdx.x * WARPS_PB + warp_in_blk;

    __shared__ float sh_val[WARPS_PB];

    // broadcast coefficient loads (all lanes same address -> 1 wavefront each)
    const float4 k0 = g_coef[3*b + 0];
    const float4 k1 = g_coef[3*b + 1];
    const float4 k2 = g_coef[3*b + 2];

    const u64 S00 = pack2(k0.x, k0.x), S11 = pack2(k0.y, k0.y), S22 = pack2(k0.z, k0.z);
    const u64 S01 = pack2(k0.w, k0.w), S02 = pack2(k1.x, k1.x), S12 = pack2(k1.y, k1.y);
    const u64 C0  = pack2(k1.z, k1.z), C1  = pack2(k1.w, k1.w), C2  = pack2(k2.x, k2.x);
    const u64 T2  = pack2(k2.y, k2.y);

    int oid = obj_ids[b];
    oid = min(max(oid, 0), NOBJ - 1);
    const ulonglong2* __restrict__ BX =
        reinterpret_cast<const ulonglong2*>(g_px) + oid * (OBJ_STRIDE / 2);
    const ulonglong2* __restrict__ BY =
        reinterpret_cast<const ulonglong2*>(g_py) + oid * (OBJ_STRIDE / 2);
    const ulonglong2* __restrict__ BZ =
        reinterpret_cast<const ulonglong2*>(g_pz) + oid * (OBJ_STRIDE / 2);

    float acc0 = 0.f, acc1 = 0.f;

    #define PAIR_TERM(PX, PY, PZ, ACC) do {                                    \
        u64 U  = fma2(S02, (PZ), fma2(S01, (PY), mul2(S00, (PX))));            \
        u64 V  = fma2(S12, (PZ), mul2(S11, (PY)));                             \
        u64 W  = mul2(S22, (PZ));                                              \
        u64 A2 = fma2((PZ), W, fma2((PY), V, mul2((PX), U)));                  \
        u64 LIN = fma2(C0, (PX), fma2(C1, (PY), fma2(C2, (PZ), T2)));          \
        u64 B2 = add2(A2, LIN);                                                \
        float a2l, a2h, b2l, b2h;                                              \
        unpack2(a2l, a2h, A2);                                                 \
        unpack2(b2l, b2h, B2);                                                 \
        ACC += (sqrt_abs(a2l) + sqrt_abs(b2l))                                 \
             + (sqrt_abs(a2h) + sqrt_abs(b2h));                                \
    } while (0)

    // front-batch 2 quads; quads 2-3 load mid-stream (regs stay moderate)
    const ulonglong2 x0 = BX[lane],      y0 = BY[lane],      z0 = BZ[lane];
    const ulonglong2 x1 = BX[lane + 32], y1 = BY[lane + 32], z1 = BZ[lane + 32];

    PAIR_TERM(x0.x, y0.x, z0.x, acc0);
    PAIR_TERM(x0.y, y0.y, z0.y, acc1);

    const ulonglong2 x2 = BX[lane + 64], y2 = BY[lane + 64], z2 = BZ[lane + 64];
    PAIR_TERM(x1.x, y1.x, z1.x, acc0);
    PAIR_TERM(x1.y, y1.y, z1.y, acc1);

    if (lane < NQUADS - 96) {   // lane < 29
        const ulonglong2 x3 = BX[lane + 96], y3 = BY[lane + 96], z3 = BZ[lane + 96];
        PAIR_TERM(x2.x, y2.x, z2.x, acc0);
        PAIR_TERM(x2.y, y2.y, z2.y, acc1);
        PAIR_TERM(x3.x, y3.x, z3.x, acc0);
        PAIR_TERM(x3.y, y3.y, z3.y, acc1);
    } else {
        PAIR_TERM(x2.x, y2.x, z2.x, acc0);
        PAIR_TERM(x2.y, y2.y, z2.y, acc1);
    }
    #undef PAIR_TERM

    float s = acc0 + acc1;

    #pragma unroll
    for (int off = 16; off > 0; off >>= 1)
        s += __shfl_down_sync(0xffffffffu, s, off);

    if (lane == 0)
        sh_val[warp_in_blk] = s * (1.0f / NPTS);
    __syncthreads();

    if (threadIdx.x == 0) {
        float blk = 0.f;
        #pragma unroll
        for (int w = 0; w < WARPS_PB; w++) blk += sh_val[w];

        const u64 q = (u64)__double2ll_rn((double)blk * FP_SCALE);
        atomicAdd(&g_sum, q);
        __threadfence();
        const unsigned int ticket = atomicAdd(&g_count, 1u);
        if (ticket == NBLOCKS - 1) {
            const u64 total = atomicExch(&g_sum, 0ULL);  // read + reset for replay
            g_count = 0u;
            out[0] = (float)((double)total * INV_FP_SCALE * (1.0 / BATCH));
        }
    }
}

extern "C" void kernel_launch(void* const* d_in, const int* in_sizes, int n_in,
                              void* d_out, int out_size)
{
    const float* pred_r  = (const float*)d_in[0];
    const float* pred_t  = (const float*)d_in[1];
    const float* gt_r    = (const float*)d_in[2];
    const float* gt_t    = (const float*)d_in[3];
    const int*   obj_ids = (const int*)  d_in[4];
    const float* points  = (const float*)d_in[5];
    float* out = (float*)d_out;

    addloss_setup<<<SETUP_BLOCKS + NOBJ, 256>>>(points, pred_r, pred_t, gt_r, gt_t);
    addloss_main<<<NBLOCKS, THREADS_PB>>>(obj_ids, out);
}